// round 5
// baseline (speedup 1.0000x reference)
#include <cuda_runtime.h>
#include <cstdint>

// Problem constants
constexpr int NB = 8;      // batch
constexpr int T  = 1024;   // sequence
constexpr int D  = 512;    // model dim
constexpr int H  = 8;      // heads
constexpr int HD = 64;     // head dim
constexpr int M  = NB * T; // 8192 rows

// ---------------- scratch (device globals; allocation-free at runtime) -------
__device__ float g_xn[M * D];
__device__ float g_qu[M * D];
__device__ float g_qv[M * D];
__device__ float g_k [M * D];
__device__ float g_v [M * D];
__device__ float g_p [M * D];
__device__ float g_ctx[M * D];
__device__ float g_bd[(size_t)NB * H * T * T];

// ---------------- tf32 helpers ----------------------------------------------
__device__ __forceinline__ uint32_t f2tf(float f) {
    uint32_t u; asm("cvt.rna.tf32.f32 %0, %1;" : "=r"(u) : "f"(f)); return u;
}
__device__ __forceinline__ void mma8(float* c, const uint32_t* a, const uint32_t* b) {
    asm volatile(
        "mma.sync.aligned.m16n8k8.row.col.f32.tf32.tf32.f32 "
        "{%0,%1,%2,%3}, {%4,%5,%6,%7}, {%8,%9}, {%0,%1,%2,%3};\n"
        : "+f"(c[0]), "+f"(c[1]), "+f"(c[2]), "+f"(c[3])
        : "r"(a[0]), "r"(a[1]), "r"(a[2]), "r"(a[3]), "r"(b[0]), "r"(b[1]));
}

// ---------------- LayerNorm --------------------------------------------------
__global__ void ln_kernel(const float* __restrict__ x,
                          const float* __restrict__ gamma,
                          const float* __restrict__ beta,
                          float* __restrict__ out) {
    int row = blockIdx.x;
    int t = threadIdx.x; // 128 threads
    const float4* xr = reinterpret_cast<const float4*>(x + (size_t)row * D);
    float4 v = xr[t];
    float s = v.x + v.y + v.z + v.w;
    __shared__ float red[4], red2[4];
    #pragma unroll
    for (int o = 16; o > 0; o >>= 1) s += __shfl_xor_sync(0xffffffffu, s, o);
    if ((t & 31) == 0) red[t >> 5] = s;
    __syncthreads();
    float mu = (red[0] + red[1] + red[2] + red[3]) * (1.0f / D);
    float dx = v.x - mu, dy = v.y - mu, dz = v.z - mu, dw = v.w - mu;
    float ss = dx * dx + dy * dy + dz * dz + dw * dw;
    #pragma unroll
    for (int o = 16; o > 0; o >>= 1) ss += __shfl_xor_sync(0xffffffffu, ss, o);
    if ((t & 31) == 0) red2[t >> 5] = ss;
    __syncthreads();
    float var = (red2[0] + red2[1] + red2[2] + red2[3]) * (1.0f / D);
    float rstd = rsqrtf(var + 1e-3f);
    const float4* g4 = reinterpret_cast<const float4*>(gamma);
    const float4* b4 = reinterpret_cast<const float4*>(beta);
    float4 g = g4[t], b = b4[t];
    float4 o4;
    o4.x = dx * rstd * g.x + b.x;
    o4.y = dy * rstd * g.y + b.y;
    o4.z = dz * rstd * g.z + b.z;
    o4.w = dw * rstd * g.w + b.w;
    reinterpret_cast<float4*>(out + (size_t)row * D)[t] = o4;
}

// ---------------- tf32 SGEMM: C[M,512] = A[M,512] @ W[512,512] ---------------
__global__ void __launch_bounds__(256) sgemm512_tf32(
    const float* __restrict__ A, const float* __restrict__ W,
    const float* __restrict__ bias, const float* __restrict__ biasU,
    const float* __restrict__ resid, float* __restrict__ out1,
    const float* __restrict__ biasV, float* __restrict__ out2) {
    __shared__ uint32_t As[128][36];
    __shared__ uint32_t Bs[32][136];
    int t = threadIdx.x;
    int bm = blockIdx.y * 128, bn = blockIdx.x * 128;
    int wid = t >> 5, lane = t & 31;
    int wm = wid & 3, wn = wid >> 2;
    int g = lane >> 2, q4 = lane & 3;

    float acc[2][8][4];
    #pragma unroll
    for (int i = 0; i < 2; i++)
        #pragma unroll
        for (int j = 0; j < 8; j++)
            #pragma unroll
            for (int k = 0; k < 4; k++) acc[i][j][k] = 0.f;

    int arow = t >> 3, ac4 = (t & 7) * 4;
    int brow = t >> 5, bc4 = (t & 31) * 4;

    float4 av[4], bv[4];
    #pragma unroll
    for (int p = 0; p < 4; p++)
        av[p] = *reinterpret_cast<const float4*>(A + (size_t)(bm + arow + p * 32) * D + ac4);
    #pragma unroll
    for (int p = 0; p < 4; p++)
        bv[p] = *reinterpret_cast<const float4*>(W + (size_t)(brow + p * 8) * D + bn + bc4);

    for (int k0 = 0; k0 < D; k0 += 32) {
        __syncthreads();
        #pragma unroll
        for (int p = 0; p < 4; p++) {
            int r = arow + p * 32;
            As[r][ac4 + 0] = f2tf(av[p].x); As[r][ac4 + 1] = f2tf(av[p].y);
            As[r][ac4 + 2] = f2tf(av[p].z); As[r][ac4 + 3] = f2tf(av[p].w);
        }
        #pragma unroll
        for (int p = 0; p < 4; p++) {
            int r = brow + p * 8;
            Bs[r][bc4 + 0] = f2tf(bv[p].x); Bs[r][bc4 + 1] = f2tf(bv[p].y);
            Bs[r][bc4 + 2] = f2tf(bv[p].z); Bs[r][bc4 + 3] = f2tf(bv[p].w);
        }
        __syncthreads();
        if (k0 + 32 < D) {
            #pragma unroll
            for (int p = 0; p < 4; p++)
                av[p] = *reinterpret_cast<const float4*>(A + (size_t)(bm + arow + p * 32) * D + k0 + 32 + ac4);
            #pragma unroll
            for (int p = 0; p < 4; p++)
                bv[p] = *reinterpret_cast<const float4*>(W + (size_t)(k0 + 32 + brow + p * 8) * D + bn + bc4);
        }
        #pragma unroll
        for (int kc = 0; kc < 4; kc++) {
            int kb = kc * 8;
            uint32_t af[2][4];
            #pragma unroll
            for (int mt = 0; mt < 2; mt++) {
                int r = wm * 32 + mt * 16 + g;
                af[mt][0] = As[r][kb + q4];      af[mt][1] = As[r + 8][kb + q4];
                af[mt][2] = As[r][kb + q4 + 4];  af[mt][3] = As[r + 8][kb + q4 + 4];
            }
            #pragma unroll
            for (int nt = 0; nt < 8; nt++) {
                int c = wn * 64 + nt * 8 + g;
                uint32_t bf[2];
                bf[0] = Bs[kb + q4][c]; bf[1] = Bs[kb + q4 + 4][c];
                mma8(acc[0][nt], af[0], bf);
                mma8(acc[1][nt], af[1], bf);
            }
        }
    }

    #pragma unroll
    for (int mt = 0; mt < 2; mt++) {
        int r0 = bm + wm * 32 + mt * 16 + g;
        #pragma unroll
        for (int nt = 0; nt < 8; nt++) {
            int c0 = bn + wn * 64 + nt * 8 + q4 * 2;
            #pragma unroll
            for (int rr = 0; rr < 2; rr++) {
                int r = r0 + rr * 8;
                float b0 = acc[mt][nt][rr * 2 + 0];
                float b1 = acc[mt][nt][rr * 2 + 1];
                if (bias) { b0 += bias[c0]; b1 += bias[c0 + 1]; }
                float v0 = b0, v1 = b1;
                if (biasU) { v0 += biasU[c0]; v1 += biasU[c0 + 1]; }
                if (resid) {
                    float2 rv = *reinterpret_cast<const float2*>(resid + (size_t)r * D + c0);
                    v0 += rv.x; v1 += rv.y;
                }
                *reinterpret_cast<float2*>(out1 + (size_t)r * D + c0) = make_float2(v0, v1);
                if (out2) {
                    float w0 = b0 + biasV[c0], w1 = b1 + biasV[c0 + 1];
                    *reinterpret_cast<float2*>(out2 + (size_t)r * D + c0) = make_float2(w0, w1);
                }
            }
        }
    }
}

// ---------------- tf32 score GEMM (for BD): S[bh,i,j] = sum_c Qv[i,c]*P[j,c] -
__global__ void __launch_bounds__(256) score_tf32(
    const float* __restrict__ Qx, const float* __restrict__ Kx, float* __restrict__ S) {
    extern __shared__ uint32_t sm4[];
    uint32_t (*Qs)[68] = reinterpret_cast<uint32_t(*)[68]>(sm4);
    uint32_t (*Ks)[68] = reinterpret_cast<uint32_t(*)[68]>(sm4 + 128 * 68);
    int bh = blockIdx.y;
    int b = bh >> 3, h = bh & 7;
    int i0 = blockIdx.x * 128;
    const float* Qb = Qx + (size_t)b * T * D + h * HD;
    const float* Kb = Kx + (size_t)b * T * D + h * HD;
    int t = threadIdx.x, wid = t >> 5, lane = t & 31;
    int wm = wid & 3, wn = wid >> 2;
    int g = lane >> 2, q4 = lane & 3;
    int lrow = t >> 4, lc4 = (t & 15) * 4;

    #pragma unroll
    for (int p = 0; p < 8; p++) {
        int r = lrow + p * 16;
        float4 v = *reinterpret_cast<const float4*>(Qb + (size_t)(i0 + r) * D + lc4);
        Qs[r][lc4 + 0] = f2tf(v.x); Qs[r][lc4 + 1] = f2tf(v.y);
        Qs[r][lc4 + 2] = f2tf(v.z); Qs[r][lc4 + 3] = f2tf(v.w);
    }

    for (int j0 = 0; j0 < T; j0 += 128) {
        __syncthreads();
        #pragma unroll
        for (int p = 0; p < 8; p++) {
            int r = lrow + p * 16;
            float4 v = *reinterpret_cast<const float4*>(Kb + (size_t)(j0 + r) * D + lc4);
            Ks[r][lc4 + 0] = f2tf(v.x); Ks[r][lc4 + 1] = f2tf(v.y);
            Ks[r][lc4 + 2] = f2tf(v.z); Ks[r][lc4 + 3] = f2tf(v.w);
        }
        __syncthreads();

        float acc[2][8][4];
        #pragma unroll
        for (int i = 0; i < 2; i++)
            #pragma unroll
            for (int j = 0; j < 8; j++)
                #pragma unroll
                for (int k = 0; k < 4; k++) acc[i][j][k] = 0.f;

        #pragma unroll
        for (int kc = 0; kc < 8; kc++) {
            int kb = kc * 8;
            uint32_t af[2][4];
            #pragma unroll
            for (int mt = 0; mt < 2; mt++) {
                int r = wm * 32 + mt * 16 + g;
                af[mt][0] = Qs[r][kb + q4];      af[mt][1] = Qs[r + 8][kb + q4];
                af[mt][2] = Qs[r][kb + q4 + 4];  af[mt][3] = Qs[r + 8][kb + q4 + 4];
            }
            #pragma unroll
            for (int nt = 0; nt < 8; nt++) {
                int c = wn * 64 + nt * 8 + g;
                uint32_t bf[2];
                bf[0] = Ks[c][kb + q4]; bf[1] = Ks[c][kb + q4 + 4];
                mma8(acc[0][nt], af[0], bf);
                mma8(acc[1][nt], af[1], bf);
            }
        }

        #pragma unroll
        for (int mt = 0; mt < 2; mt++) {
            int r0 = i0 + wm * 32 + mt * 16 + g;
            #pragma unroll
            for (int nt = 0; nt < 8; nt++) {
                int c0 = j0 + wn * 64 + nt * 8 + q4 * 2;
                size_t base = ((size_t)bh * T + r0) * T + c0;
                *reinterpret_cast<float2*>(S + base) =
                    make_float2(acc[mt][nt][0], acc[mt][nt][1]);
                *reinterpret_cast<float2*>(S + base + (size_t)8 * T) =
                    make_float2(acc[mt][nt][2], acc[mt][nt][3]);
            }
        }
    }
}

// ---------------- fused flash attention: content + shift + softmax + P@V -----
// Per CTA: bh, i-tile of 128. Stream j-tiles of 64. 256 thr, 8 warps (4m x 2n).
constexpr int QS_OFF = 0;
constexpr int KS_OFF = QS_OFF + 128 * 68;
constexpr int VS_OFF = KS_OFF + 64 * 68;
constexpr int PS_OFF = VS_OFF + 64 * 72;
constexpr int RM_OFF = PS_OFF + 128 * 68;
constexpr int RS_OFF = RM_OFF + 256;
constexpr int FLASH_SMEM_U32 = RS_OFF + 256;

__global__ void __launch_bounds__(256) flash_attn(
    const float* __restrict__ Qu, const float* __restrict__ Kx,
    const float* __restrict__ Vx, const float* __restrict__ BD,
    float* __restrict__ ctx) {
    extern __shared__ uint32_t sm4[];
    uint32_t (*Qs)[68] = reinterpret_cast<uint32_t(*)[68]>(sm4 + QS_OFF);
    uint32_t (*Ks)[68] = reinterpret_cast<uint32_t(*)[68]>(sm4 + KS_OFF);
    uint32_t (*Vs)[72] = reinterpret_cast<uint32_t(*)[72]>(sm4 + VS_OFF);
    float    (*Ps)[68] = reinterpret_cast<float(*)[68]>(sm4 + PS_OFF);
    float* redM = reinterpret_cast<float*>(sm4 + RM_OFF); // [2][128]
    float* redS = reinterpret_cast<float*>(sm4 + RS_OFF); // [2][128]

    int bh = blockIdx.y;
    int b = bh >> 3, h = bh & 7;
    int i0 = blockIdx.x * 128;
    const float* Qb = Qu + (size_t)b * T * D + h * HD;
    const float* Kb = Kx + (size_t)b * T * D + h * HD;
    const float* Vb = Vx + (size_t)b * T * D + h * HD;
    const float* BDb = BD + (size_t)bh * T * T;

    int t = threadIdx.x, wid = t >> 5, lane = t & 31;
    int wm = wid & 3, wn = wid >> 2;
    int g = lane >> 2, q4 = lane & 3;

    // load Q tile (128 x 64) -> Qs as tf32
    // each thread covers 32 consecutive columns (lc0..lc0+31) of its row
    {
        int lrow = t >> 1, lc0 = (t & 1) * 32;
        #pragma unroll
        for (int p = 0; p < 4; p++) {
            int c = lc0 + p * 8;
            float4 v = *reinterpret_cast<const float4*>(Qb + (size_t)(i0 + lrow) * D + c);
            Qs[lrow][c + 0] = f2tf(v.x); Qs[lrow][c + 1] = f2tf(v.y);
            Qs[lrow][c + 2] = f2tf(v.z); Qs[lrow][c + 3] = f2tf(v.w);
            float4 v2 = *reinterpret_cast<const float4*>(Qb + (size_t)(i0 + lrow) * D + c + 4);
            Qs[lrow][c + 4] = f2tf(v2.x); Qs[lrow][c + 5] = f2tf(v2.y);
            Qs[lrow][c + 6] = f2tf(v2.z); Qs[lrow][c + 7] = f2tf(v2.w);
        }
    }

    float m_st[2][2], l_st[2][2];
    #pragma unroll
    for (int a = 0; a < 2; a++)
        #pragma unroll
        for (int c = 0; c < 2; c++) { m_st[a][c] = -1e30f; l_st[a][c] = 0.f; }
    float o_acc[2][4][4];
    #pragma unroll
    for (int i = 0; i < 2; i++)
        #pragma unroll
        for (int j = 0; j < 4; j++)
            #pragma unroll
            for (int k = 0; k < 4; k++) o_acc[i][j][k] = 0.f;

    int kvrow = t >> 2, kvc4 = (t & 3) * 4;

    for (int j0 = 0; j0 < T; j0 += 64) {
        __syncthreads();

        #pragma unroll
        for (int p = 0; p < 4; p++) {
            int c = kvc4 + p * 16;
            float4 kv = *reinterpret_cast<const float4*>(Kb + (size_t)(j0 + kvrow) * D + c);
            Ks[kvrow][c + 0] = f2tf(kv.x); Ks[kvrow][c + 1] = f2tf(kv.y);
            Ks[kvrow][c + 2] = f2tf(kv.z); Ks[kvrow][c + 3] = f2tf(kv.w);
            float4 vv = *reinterpret_cast<const float4*>(Vb + (size_t)(j0 + kvrow) * D + c);
            Vs[kvrow][c + 0] = f2tf(vv.x); Vs[kvrow][c + 1] = f2tf(vv.y);
            Vs[kvrow][c + 2] = f2tf(vv.z); Vs[kvrow][c + 3] = f2tf(vv.w);
        }
        #pragma unroll
        for (int e0 = 0; e0 < 8192; e0 += 256) {
            int e = e0 + t;
            int r = e >> 6, c = e & 63;
            int i = i0 + r, j = j0 + c;
            float sh;
            if (j <= i)          sh = BDb[(size_t)i * T + (j - i + T - 1)];
            else if (j == i + 1) sh = 0.f;
            else                 sh = BDb[(size_t)(i + 1) * T + (j - i - 2)];
            Ps[r][c] = sh;
        }
        __syncthreads();

        float acc[2][4][4];
        #pragma unroll
        for (int i = 0; i < 2; i++)
            #pragma unroll
            for (int j = 0; j < 4; j++)
                #pragma unroll
                for (int k = 0; k < 4; k++) acc[i][j][k] = 0.f;
        #pragma unroll
        for (int kc = 0; kc < 8; kc++) {
            int kb = kc * 8;
            uint32_t af[2][4];
            #pragma unroll
            for (int mt = 0; mt < 2; mt++) {
                int r = wm * 32 + mt * 16 + g;
                af[mt][0] = Qs[r][kb + q4];      af[mt][1] = Qs[r + 8][kb + q4];
                af[mt][2] = Qs[r][kb + q4 + 4];  af[mt][3] = Qs[r + 8][kb + q4 + 4];
            }
            #pragma unroll
            for (int nt = 0; nt < 4; nt++) {
                int c = wn * 32 + nt * 8 + g;
                uint32_t bf[2];
                bf[0] = Ks[c][kb + q4]; bf[1] = Ks[c][kb + q4 + 4];
                mma8(acc[0][nt], af[0], bf);
                mma8(acc[1][nt], af[1], bf);
            }
        }

        #pragma unroll
        for (int mt = 0; mt < 2; mt++) {
            #pragma unroll
            for (int rr = 0; rr < 2; rr++) {
                int r = wm * 32 + mt * 16 + g + rr * 8;
                float mx = -1e30f;
                #pragma unroll
                for (int nt = 0; nt < 4; nt++) {
                    int c = wn * 32 + nt * 8 + q4 * 2;
                    float v0 = (acc[mt][nt][rr * 2 + 0] + Ps[r][c + 0]) * 0.125f;
                    float v1 = (acc[mt][nt][rr * 2 + 1] + Ps[r][c + 1]) * 0.125f;
                    acc[mt][nt][rr * 2 + 0] = v0;
                    acc[mt][nt][rr * 2 + 1] = v1;
                    mx = fmaxf(mx, fmaxf(v0, v1));
                }
                mx = fmaxf(mx, __shfl_xor_sync(0xffffffffu, mx, 1));
                mx = fmaxf(mx, __shfl_xor_sync(0xffffffffu, mx, 2));
                if (q4 == 0) redM[wn * 128 + r] = mx;
            }
        }
        __syncthreads();

        #pragma unroll
        for (int mt = 0; mt < 2; mt++) {
            #pragma unroll
            for (int rr = 0; rr < 2; rr++) {
                int r = wm * 32 + mt * 16 + g + rr * 8;
                float tileMax = fmaxf(redM[r], redM[128 + r]);
                float m_new = fmaxf(m_st[mt][rr], tileMax);
                float scl = __expf(m_st[mt][rr] - m_new);
                m_st[mt][rr] = m_new;
                float sum = 0.f;
                #pragma unroll
                for (int nt = 0; nt < 4; nt++) {
                    int c = wn * 32 + nt * 8 + q4 * 2;
                    float p0 = __expf(acc[mt][nt][rr * 2 + 0] - m_new);
                    float p1 = __expf(acc[mt][nt][rr * 2 + 1] - m_new);
                    sum += p0 + p1;
                    Ps[r][c + 0] = __uint_as_float(f2tf(p0));
                    Ps[r][c + 1] = __uint_as_float(f2tf(p1));
                    o_acc[mt][nt][rr * 2 + 0] *= scl;
                    o_acc[mt][nt][rr * 2 + 1] *= scl;
                }
                sum += __shfl_xor_sync(0xffffffffu, sum, 1);
                sum += __shfl_xor_sync(0xffffffffu, sum, 2);
                l_st[mt][rr] *= scl;
                if (q4 == 0) redS[wn * 128 + r] = sum;
            }
        }
        __syncthreads();

        #pragma unroll
        for (int mt = 0; mt < 2; mt++) {
            #pragma unroll
            for (int rr = 0; rr < 2; rr++) {
                int r = wm * 32 + mt * 16 + g + rr * 8;
                l_st[mt][rr] += redS[r] + redS[128 + r];
            }
        }

        uint32_t (*Pu)[68] = reinterpret_cast<uint32_t(*)[68]>(Ps);
        #pragma unroll
        for (int kc = 0; kc < 8; kc++) {
            int kb = kc * 8;
            uint32_t af[2][4];
            #pragma unroll
            for (int mt = 0; mt < 2; mt++) {
                int r = wm * 32 + mt * 16 + g;
                af[mt][0] = Pu[r][kb + q4];      af[mt][1] = Pu[r + 8][kb + q4];
                af[mt][2] = Pu[r][kb + q4 + 4];  af[mt][3] = Pu[r + 8][kb + q4 + 4];
            }
            #pragma unroll
            for (int nt = 0; nt < 4; nt++) {
                int c = wn * 32 + nt * 8 + g;
                uint32_t bf[2];
                bf[0] = Vs[kb + q4][c]; bf[1] = Vs[kb + q4 + 4][c];
                mma8(o_acc[0][nt], af[0], bf);
                mma8(o_acc[1][nt], af[1], bf);
            }
        }
    }

    float* Cg = ctx + ((size_t)(b * T + i0)) * D + h * HD;
    #pragma unroll
    for (int mt = 0; mt < 2; mt++) {
        #pragma unroll
        for (int rr = 0; rr < 2; rr++) {
            int r = wm * 32 + mt * 16 + g + rr * 8;
            float inv = 1.0f / l_st[mt][rr];
            #pragma unroll
            for (int nt = 0; nt < 4; nt++) {
                int c = wn * 32 + nt * 8 + q4 * 2;
                *reinterpret_cast<float2*>(Cg + (size_t)r * D + c) =
                    make_float2(o_acc[mt][nt][rr * 2 + 0] * inv,
                                o_acc[mt][nt][rr * 2 + 1] * inv);
            }
        }
    }
}

// ---------------- launch -----------------------------------------------------
extern "C" void kernel_launch(void* const* d_in, const int* in_sizes, int n_in,
                              void* d_out, int out_size) {
    const float* inputs = (const float*)d_in[0];
    const float* pos    = (const float*)d_in[1];
    const float* gamma  = (const float*)d_in[2];
    const float* beta   = (const float*)d_in[3];
    const float* wq     = (const float*)d_in[4];
    const float* bq     = (const float*)d_in[5];
    const float* wk     = (const float*)d_in[6];
    const float* bk     = (const float*)d_in[7];
    const float* wv     = (const float*)d_in[8];
    const float* bv     = (const float*)d_in[9];
    const float* wpos   = (const float*)d_in[10];
    const float* u      = (const float*)d_in[11];
    const float* vb     = (const float*)d_in[12];
    const float* wo     = (const float*)d_in[13];
    const float* bo     = (const float*)d_in[14];
    float* out = (float*)d_out;

    float *xn, *qu, *qv, *kx, *vx, *px, *ctx, *bd;
    cudaGetSymbolAddress((void**)&xn,  g_xn);
    cudaGetSymbolAddress((void**)&qu,  g_qu);
    cudaGetSymbolAddress((void**)&qv,  g_qv);
    cudaGetSymbolAddress((void**)&kx,  g_k);
    cudaGetSymbolAddress((void**)&vx,  g_v);
    cudaGetSymbolAddress((void**)&px,  g_p);
    cudaGetSymbolAddress((void**)&ctx, g_ctx);
    cudaGetSymbolAddress((void**)&bd,  g_bd);

    const int SCORE_SMEM = 2 * 128 * 68 * 4;
    cudaFuncSetAttribute(score_tf32, cudaFuncAttributeMaxDynamicSharedMemorySize, SCORE_SMEM);
    const int FLASH_SMEM = FLASH_SMEM_U32 * 4;
    cudaFuncSetAttribute(flash_attn, cudaFuncAttributeMaxDynamicSharedMemorySize, FLASH_SMEM);

    // 1. LayerNorm
    ln_kernel<<<M, 128>>>(inputs, gamma, beta, xn);

    // 2. Projections (tf32 MMA)
    dim3 gg(4, 64);
    sgemm512_tf32<<<gg, 256>>>(xn,  wq,   bq,      u,       nullptr, qu, vb, qv);
    sgemm512_tf32<<<gg, 256>>>(xn,  wk,   bk,      nullptr, nullptr, kx, nullptr, nullptr);
    sgemm512_tf32<<<gg, 256>>>(xn,  wv,   bv,      nullptr, nullptr, vx, nullptr, nullptr);
    sgemm512_tf32<<<gg, 256>>>(pos, wpos, nullptr, nullptr, nullptr, px, nullptr, nullptr);

    // 3. BD = (Qv) @ P^T (pre-shift positional scores)
    dim3 sg(8, NB * H);
    score_tf32<<<sg, 256, SCORE_SMEM>>>(qv, px, bd);

    // 4. fused content-score + shift + softmax + P@V
    flash_attn<<<dim3(8, NB * H), 256, FLASH_SMEM>>>(qu, kx, vx, bd, ctx);

    // 5. output projection + bias + residual
    sgemm512_tf32<<<gg, 256>>>(ctx, wo, bo, nullptr, inputs, out, nullptr, nullptr);
}

// round 6
// speedup vs baseline: 2.7565x; 2.7565x over previous
#include <cuda_runtime.h>
#include <cstdint>

// Problem constants
constexpr int NB = 8;      // batch
constexpr int T  = 1024;   // sequence
constexpr int D  = 512;    // model dim
constexpr int H  = 8;      // heads
constexpr int HD = 64;     // head dim
constexpr int M  = NB * T; // 8192 rows

// ---------------- scratch (device globals; allocation-free at runtime) -------
__device__ float g_xn[M * D];
__device__ float g_qu[M * D];
__device__ float g_qv[M * D];
__device__ float g_k [M * D];
__device__ float g_v [M * D];
__device__ float g_p [M * D];
__device__ float g_ctx[M * D];
__device__ float g_expP[(size_t)NB * H * T * T];  // unnormalized exp scores
__device__ float g_bd  [(size_t)NB * H * T * T];  // positional scores (pre-shift)
__device__ float g_rowsum[NB * H * T];            // softmax denominators

// ---------------- tf32 helpers ----------------------------------------------
__device__ __forceinline__ uint32_t f2tf(float f) {
    uint32_t u; asm("cvt.rna.tf32.f32 %0, %1;" : "=r"(u) : "f"(f)); return u;
}
__device__ __forceinline__ void mma8(float* c, const uint32_t* a, const uint32_t* b) {
    asm volatile(
        "mma.sync.aligned.m16n8k8.row.col.f32.tf32.tf32.f32 "
        "{%0,%1,%2,%3}, {%4,%5,%6,%7}, {%8,%9}, {%0,%1,%2,%3};\n"
        : "+f"(c[0]), "+f"(c[1]), "+f"(c[2]), "+f"(c[3])
        : "r"(a[0]), "r"(a[1]), "r"(a[2]), "r"(a[3]), "r"(b[0]), "r"(b[1]));
}

// rel_shift lookup: shift[i][j] per Transformer-XL semantics
__device__ __forceinline__ float shift_val(const float* __restrict__ BDb, int i, int j) {
    if (j <= i)      return BDb[(size_t)i * T + (j - i + T - 1)];
    if (j == i + 1)  return 0.f;
    return BDb[(size_t)(i + 1) * T + (j - i - 2)];
}

// ---------------- LayerNorm --------------------------------------------------
__global__ void ln_kernel(const float* __restrict__ x,
                          const float* __restrict__ gamma,
                          const float* __restrict__ beta,
                          float* __restrict__ out) {
    int row = blockIdx.x;
    int t = threadIdx.x; // 128 threads
    const float4* xr = reinterpret_cast<const float4*>(x + (size_t)row * D);
    float4 v = xr[t];
    float s = v.x + v.y + v.z + v.w;
    __shared__ float red[4], red2[4];
    #pragma unroll
    for (int o = 16; o > 0; o >>= 1) s += __shfl_xor_sync(0xffffffffu, s, o);
    if ((t & 31) == 0) red[t >> 5] = s;
    __syncthreads();
    float mu = (red[0] + red[1] + red[2] + red[3]) * (1.0f / D);
    float dx = v.x - mu, dy = v.y - mu, dz = v.z - mu, dw = v.w - mu;
    float ss = dx * dx + dy * dy + dz * dz + dw * dw;
    #pragma unroll
    for (int o = 16; o > 0; o >>= 1) ss += __shfl_xor_sync(0xffffffffu, ss, o);
    if ((t & 31) == 0) red2[t >> 5] = ss;
    __syncthreads();
    float var = (red2[0] + red2[1] + red2[2] + red2[3]) * (1.0f / D);
    float rstd = rsqrtf(var + 1e-3f);
    const float4* g4 = reinterpret_cast<const float4*>(gamma);
    const float4* b4 = reinterpret_cast<const float4*>(beta);
    float4 g = g4[t], b = b4[t];
    float4 o4;
    o4.x = dx * rstd * g.x + b.x;
    o4.y = dy * rstd * g.y + b.y;
    o4.z = dz * rstd * g.z + b.z;
    o4.w = dw * rstd * g.w + b.w;
    reinterpret_cast<float4*>(out + (size_t)row * D)[t] = o4;
}

// ---------------- tf32 SGEMM: C[M,512] = A[M,512] @ W[512,512] ---------------
__global__ void __launch_bounds__(256) sgemm512_tf32(
    const float* __restrict__ A, const float* __restrict__ W,
    const float* __restrict__ bias, const float* __restrict__ biasU,
    const float* __restrict__ resid, float* __restrict__ out1,
    const float* __restrict__ biasV, float* __restrict__ out2) {
    __shared__ uint32_t As[128][36];
    __shared__ uint32_t Bs[32][136];
    int t = threadIdx.x;
    int bm = blockIdx.y * 128, bn = blockIdx.x * 128;
    int wid = t >> 5, lane = t & 31;
    int wm = wid & 3, wn = wid >> 2;
    int g = lane >> 2, q4 = lane & 3;

    float acc[2][8][4];
    #pragma unroll
    for (int i = 0; i < 2; i++)
        #pragma unroll
        for (int j = 0; j < 8; j++)
            #pragma unroll
            for (int k = 0; k < 4; k++) acc[i][j][k] = 0.f;

    int arow = t >> 3, ac4 = (t & 7) * 4;
    int brow = t >> 5, bc4 = (t & 31) * 4;

    float4 av[4], bv[4];
    #pragma unroll
    for (int p = 0; p < 4; p++)
        av[p] = *reinterpret_cast<const float4*>(A + (size_t)(bm + arow + p * 32) * D + ac4);
    #pragma unroll
    for (int p = 0; p < 4; p++)
        bv[p] = *reinterpret_cast<const float4*>(W + (size_t)(brow + p * 8) * D + bn + bc4);

    for (int k0 = 0; k0 < D; k0 += 32) {
        __syncthreads();
        #pragma unroll
        for (int p = 0; p < 4; p++) {
            int r = arow + p * 32;
            As[r][ac4 + 0] = f2tf(av[p].x); As[r][ac4 + 1] = f2tf(av[p].y);
            As[r][ac4 + 2] = f2tf(av[p].z); As[r][ac4 + 3] = f2tf(av[p].w);
        }
        #pragma unroll
        for (int p = 0; p < 4; p++) {
            int r = brow + p * 8;
            Bs[r][bc4 + 0] = f2tf(bv[p].x); Bs[r][bc4 + 1] = f2tf(bv[p].y);
            Bs[r][bc4 + 2] = f2tf(bv[p].z); Bs[r][bc4 + 3] = f2tf(bv[p].w);
        }
        __syncthreads();
        if (k0 + 32 < D) {
            #pragma unroll
            for (int p = 0; p < 4; p++)
                av[p] = *reinterpret_cast<const float4*>(A + (size_t)(bm + arow + p * 32) * D + k0 + 32 + ac4);
            #pragma unroll
            for (int p = 0; p < 4; p++)
                bv[p] = *reinterpret_cast<const float4*>(W + (size_t)(k0 + 32 + brow + p * 8) * D + bn + bc4);
        }
        #pragma unroll
        for (int kc = 0; kc < 4; kc++) {
            int kb = kc * 8;
            uint32_t af[2][4];
            #pragma unroll
            for (int mt = 0; mt < 2; mt++) {
                int r = wm * 32 + mt * 16 + g;
                af[mt][0] = As[r][kb + q4];      af[mt][1] = As[r + 8][kb + q4];
                af[mt][2] = As[r][kb + q4 + 4];  af[mt][3] = As[r + 8][kb + q4 + 4];
            }
            #pragma unroll
            for (int nt = 0; nt < 8; nt++) {
                int c = wn * 64 + nt * 8 + g;
                uint32_t bf[2];
                bf[0] = Bs[kb + q4][c]; bf[1] = Bs[kb + q4 + 4][c];
                mma8(acc[0][nt], af[0], bf);
                mma8(acc[1][nt], af[1], bf);
            }
        }
    }

    #pragma unroll
    for (int mt = 0; mt < 2; mt++) {
        int r0 = bm + wm * 32 + mt * 16 + g;
        #pragma unroll
        for (int nt = 0; nt < 8; nt++) {
            int c0 = bn + wn * 64 + nt * 8 + q4 * 2;
            #pragma unroll
            for (int rr = 0; rr < 2; rr++) {
                int r = r0 + rr * 8;
                float b0 = acc[mt][nt][rr * 2 + 0];
                float b1 = acc[mt][nt][rr * 2 + 1];
                if (bias) { b0 += bias[c0]; b1 += bias[c0 + 1]; }
                float v0 = b0, v1 = b1;
                if (biasU) { v0 += biasU[c0]; v1 += biasU[c0 + 1]; }
                if (resid) {
                    float2 rv = *reinterpret_cast<const float2*>(resid + (size_t)r * D + c0);
                    v0 += rv.x; v1 += rv.y;
                }
                *reinterpret_cast<float2*>(out1 + (size_t)r * D + c0) = make_float2(v0, v1);
                if (out2) {
                    float w0 = b0 + biasV[c0], w1 = b1 + biasV[c0 + 1];
                    *reinterpret_cast<float2*>(out2 + (size_t)r * D + c0) = make_float2(w0, w1);
                }
            }
        }
    }
}

// ---------------- tf32 score GEMM (for BD): bd[bh,i,j] = sum_c Qv[i,c]*P[j,c]
__global__ void __launch_bounds__(256) score_tf32(
    const float* __restrict__ Qx, const float* __restrict__ Kx, float* __restrict__ S) {
    extern __shared__ uint32_t sm4[];
    uint32_t (*Qs)[68] = reinterpret_cast<uint32_t(*)[68]>(sm4);
    uint32_t (*Ks)[68] = reinterpret_cast<uint32_t(*)[68]>(sm4 + 128 * 68);
    int bh = blockIdx.y;
    int b = bh >> 3, h = bh & 7;
    int i0 = blockIdx.x * 128;
    const float* Qb = Qx + (size_t)b * T * D + h * HD;
    const float* Kb = Kx + (size_t)b * T * D + h * HD;
    int t = threadIdx.x, wid = t >> 5, lane = t & 31;
    int wm = wid & 3, wn = wid >> 2;
    int g = lane >> 2, q4 = lane & 3;
    int lrow = t >> 4, lc4 = (t & 15) * 4;

    #pragma unroll
    for (int p = 0; p < 8; p++) {
        int r = lrow + p * 16;
        float4 v = *reinterpret_cast<const float4*>(Qb + (size_t)(i0 + r) * D + lc4);
        Qs[r][lc4 + 0] = f2tf(v.x); Qs[r][lc4 + 1] = f2tf(v.y);
        Qs[r][lc4 + 2] = f2tf(v.z); Qs[r][lc4 + 3] = f2tf(v.w);
    }

    for (int j0 = 0; j0 < T; j0 += 128) {
        __syncthreads();
        #pragma unroll
        for (int p = 0; p < 8; p++) {
            int r = lrow + p * 16;
            float4 v = *reinterpret_cast<const float4*>(Kb + (size_t)(j0 + r) * D + lc4);
            Ks[r][lc4 + 0] = f2tf(v.x); Ks[r][lc4 + 1] = f2tf(v.y);
            Ks[r][lc4 + 2] = f2tf(v.z); Ks[r][lc4 + 3] = f2tf(v.w);
        }
        __syncthreads();

        float acc[2][8][4];
        #pragma unroll
        for (int i = 0; i < 2; i++)
            #pragma unroll
            for (int j = 0; j < 8; j++)
                #pragma unroll
                for (int k = 0; k < 4; k++) acc[i][j][k] = 0.f;

        #pragma unroll
        for (int kc = 0; kc < 8; kc++) {
            int kb = kc * 8;
            uint32_t af[2][4];
            #pragma unroll
            for (int mt = 0; mt < 2; mt++) {
                int r = wm * 32 + mt * 16 + g;
                af[mt][0] = Qs[r][kb + q4];      af[mt][1] = Qs[r + 8][kb + q4];
                af[mt][2] = Qs[r][kb + q4 + 4];  af[mt][3] = Qs[r + 8][kb + q4 + 4];
            }
            #pragma unroll
            for (int nt = 0; nt < 8; nt++) {
                int c = wn * 64 + nt * 8 + g;
                uint32_t bf[2];
                bf[0] = Ks[c][kb + q4]; bf[1] = Ks[c][kb + q4 + 4];
                mma8(acc[0][nt], af[0], bf);
                mma8(acc[1][nt], af[1], bf);
            }
        }

        #pragma unroll
        for (int mt = 0; mt < 2; mt++) {
            int r0 = i0 + wm * 32 + mt * 16 + g;
            #pragma unroll
            for (int nt = 0; nt < 8; nt++) {
                int c0 = j0 + wn * 64 + nt * 8 + q4 * 2;
                size_t base = ((size_t)bh * T + r0) * T + c0;
                *reinterpret_cast<float2*>(S + base) =
                    make_float2(acc[mt][nt][0], acc[mt][nt][1]);
                *reinterpret_cast<float2*>(S + base + (size_t)8 * T) =
                    make_float2(acc[mt][nt][2], acc[mt][nt][3]);
            }
        }
    }
}

// -------- fused content score + shift + exp + rowsum: expP = exp((QuK^T+shift)/8)
// Same GEMM structure as score_tf32; epilogue applies shifted BD, exp (no max
// subtraction: logits bounded), accumulates per-row sums across j-tiles, and
// writes unnormalized expP. Row sums written to rowsum[bh*T + i] at the end.
__global__ void __launch_bounds__(256) score_softmax_tf32(
    const float* __restrict__ Qx, const float* __restrict__ Kx,
    const float* __restrict__ BD, float* __restrict__ S,
    float* __restrict__ rowsum) {
    extern __shared__ uint32_t sm4[];
    uint32_t (*Qs)[68] = reinterpret_cast<uint32_t(*)[68]>(sm4);
    uint32_t (*Ks)[68] = reinterpret_cast<uint32_t(*)[68]>(sm4 + 128 * 68);
    float* redS = reinterpret_cast<float*>(sm4 + 2 * 128 * 68); // [2][128]
    int bh = blockIdx.y;
    int b = bh >> 3, h = bh & 7;
    int i0 = blockIdx.x * 128;
    const float* Qb = Qx + (size_t)b * T * D + h * HD;
    const float* Kb = Kx + (size_t)b * T * D + h * HD;
    const float* BDb = BD + (size_t)bh * T * T;
    int t = threadIdx.x, wid = t >> 5, lane = t & 31;
    int wm = wid & 3, wn = wid >> 2;
    int g = lane >> 2, q4 = lane & 3;
    int lrow = t >> 4, lc4 = (t & 15) * 4;

    #pragma unroll
    for (int p = 0; p < 8; p++) {
        int r = lrow + p * 16;
        float4 v = *reinterpret_cast<const float4*>(Qb + (size_t)(i0 + r) * D + lc4);
        Qs[r][lc4 + 0] = f2tf(v.x); Qs[r][lc4 + 1] = f2tf(v.y);
        Qs[r][lc4 + 2] = f2tf(v.z); Qs[r][lc4 + 3] = f2tf(v.w);
    }

    float rs[2][2] = {{0.f, 0.f}, {0.f, 0.f}}; // per-row partial sums

    for (int j0 = 0; j0 < T; j0 += 128) {
        __syncthreads();
        #pragma unroll
        for (int p = 0; p < 8; p++) {
            int r = lrow + p * 16;
            float4 v = *reinterpret_cast<const float4*>(Kb + (size_t)(j0 + r) * D + lc4);
            Ks[r][lc4 + 0] = f2tf(v.x); Ks[r][lc4 + 1] = f2tf(v.y);
            Ks[r][lc4 + 2] = f2tf(v.z); Ks[r][lc4 + 3] = f2tf(v.w);
        }
        __syncthreads();

        float acc[2][8][4];
        #pragma unroll
        for (int i = 0; i < 2; i++)
            #pragma unroll
            for (int j = 0; j < 8; j++)
                #pragma unroll
                for (int k = 0; k < 4; k++) acc[i][j][k] = 0.f;

        #pragma unroll
        for (int kc = 0; kc < 8; kc++) {
            int kb = kc * 8;
            uint32_t af[2][4];
            #pragma unroll
            for (int mt = 0; mt < 2; mt++) {
                int r = wm * 32 + mt * 16 + g;
                af[mt][0] = Qs[r][kb + q4];      af[mt][1] = Qs[r + 8][kb + q4];
                af[mt][2] = Qs[r][kb + q4 + 4];  af[mt][3] = Qs[r + 8][kb + q4 + 4];
            }
            #pragma unroll
            for (int nt = 0; nt < 8; nt++) {
                int c = wn * 64 + nt * 8 + g;
                uint32_t bf[2];
                bf[0] = Ks[c][kb + q4]; bf[1] = Ks[c][kb + q4 + 4];
                mma8(acc[0][nt], af[0], bf);
                mma8(acc[1][nt], af[1], bf);
            }
        }

        // epilogue: shift + exp + rowsum + store expP
        #pragma unroll
        for (int mt = 0; mt < 2; mt++) {
            int r0 = i0 + wm * 32 + mt * 16 + g;
            #pragma unroll
            for (int nt = 0; nt < 8; nt++) {
                int c0 = j0 + wn * 64 + nt * 8 + q4 * 2;
                #pragma unroll
                for (int rr = 0; rr < 2; rr++) {
                    int r = r0 + rr * 8;
                    float sh0 = shift_val(BDb, r, c0);
                    float sh1 = shift_val(BDb, r, c0 + 1);
                    float e0 = __expf((acc[mt][nt][rr * 2 + 0] + sh0) * 0.125f);
                    float e1 = __expf((acc[mt][nt][rr * 2 + 1] + sh1) * 0.125f);
                    rs[mt][rr] += e0 + e1;
                    *reinterpret_cast<float2*>(S + ((size_t)bh * T + r) * T + c0) =
                        make_float2(e0, e1);
                }
            }
        }
    }

    // reduce row sums: quad lanes (q4) -> smem cross-wn -> gmem
    #pragma unroll
    for (int mt = 0; mt < 2; mt++) {
        #pragma unroll
        for (int rr = 0; rr < 2; rr++) {
            float s = rs[mt][rr];
            s += __shfl_xor_sync(0xffffffffu, s, 1);
            s += __shfl_xor_sync(0xffffffffu, s, 2);
            int r = wm * 32 + mt * 16 + g + rr * 8; // local row 0..127
            if (q4 == 0) redS[wn * 128 + r] = s;
        }
    }
    __syncthreads();
    if (wn == 0 && q4 == 0) {
        #pragma unroll
        for (int mt = 0; mt < 2; mt++) {
            #pragma unroll
            for (int rr = 0; rr < 2; rr++) {
                int r = wm * 32 + mt * 16 + g + rr * 8;
                rowsum[(size_t)bh * T + i0 + r] = redS[r] + redS[128 + r];
            }
        }
    }
}

// ---------------- tf32 attn @ V: ctx[i,f] = (sum_j expP[i,j] V[j,f]) / rowsum[i]
__global__ void __launch_bounds__(256) attnv_tf32(
    const float* __restrict__ S, const float* __restrict__ V,
    const float* __restrict__ rowsum, float* __restrict__ ctx) {
    __shared__ uint32_t As[128][36];  // expP tile, [m][k], pitch 36
    __shared__ uint32_t Vs[32][72];   // V tile, [k=j][n=f], pitch 72
    int bh = blockIdx.y;
    int b = bh >> 3, h = bh & 7;
    int i0 = blockIdx.x * 128;
    const float* Sb = S + ((size_t)bh * T + i0) * T;
    const float* Vb = V + (size_t)b * T * D + h * HD;
    int t = threadIdx.x, wid = t >> 5, lane = t & 31;
    int wm = wid & 3, wn = wid >> 2;
    int g = lane >> 2, q4 = lane & 3;

    int srow = t >> 3, sc4 = (t & 7) * 4;
    int vrow = t >> 4, vc4 = (t & 15) * 4;

    float acc[2][4][4];
    #pragma unroll
    for (int i = 0; i < 2; i++)
        #pragma unroll
        for (int j = 0; j < 4; j++)
            #pragma unroll
            for (int k = 0; k < 4; k++) acc[i][j][k] = 0.f;

    float4 sv[4], vv[2];
    #pragma unroll
    for (int p = 0; p < 4; p++)
        sv[p] = *reinterpret_cast<const float4*>(Sb + (size_t)(srow + p * 32) * T + sc4);
    #pragma unroll
    for (int p = 0; p < 2; p++)
        vv[p] = *reinterpret_cast<const float4*>(Vb + (size_t)(vrow + p * 16) * D + vc4);

    for (int k0 = 0; k0 < T; k0 += 32) {
        __syncthreads();
        #pragma unroll
        for (int p = 0; p < 4; p++) {
            int r = srow + p * 32;
            As[r][sc4 + 0] = f2tf(sv[p].x); As[r][sc4 + 1] = f2tf(sv[p].y);
            As[r][sc4 + 2] = f2tf(sv[p].z); As[r][sc4 + 3] = f2tf(sv[p].w);
        }
        #pragma unroll
        for (int p = 0; p < 2; p++) {
            int r = vrow + p * 16;
            Vs[r][vc4 + 0] = f2tf(vv[p].x); Vs[r][vc4 + 1] = f2tf(vv[p].y);
            Vs[r][vc4 + 2] = f2tf(vv[p].z); Vs[r][vc4 + 3] = f2tf(vv[p].w);
        }
        __syncthreads();
        if (k0 + 32 < T) {
            #pragma unroll
            for (int p = 0; p < 4; p++)
                sv[p] = *reinterpret_cast<const float4*>(Sb + (size_t)(srow + p * 32) * T + k0 + 32 + sc4);
            #pragma unroll
            for (int p = 0; p < 2; p++)
                vv[p] = *reinterpret_cast<const float4*>(Vb + (size_t)(k0 + 32 + vrow + p * 16) * D + vc4);
        }
        #pragma unroll
        for (int kc = 0; kc < 4; kc++) {
            int kb = kc * 8;
            uint32_t af[2][4];
            #pragma unroll
            for (int mt = 0; mt < 2; mt++) {
                int r = wm * 32 + mt * 16 + g;
                af[mt][0] = As[r][kb + q4];      af[mt][1] = As[r + 8][kb + q4];
                af[mt][2] = As[r][kb + q4 + 4];  af[mt][3] = As[r + 8][kb + q4 + 4];
            }
            #pragma unroll
            for (int nt = 0; nt < 4; nt++) {
                int c = wn * 32 + nt * 8 + g;
                uint32_t bf[2];
                bf[0] = Vs[kb + q4][c]; bf[1] = Vs[kb + q4 + 4][c];
                mma8(acc[0][nt], af[0], bf);
                mma8(acc[1][nt], af[1], bf);
            }
        }
    }

    const float* rsb = rowsum + (size_t)bh * T + i0;
    float* Cg = ctx + ((size_t)(b * T + i0)) * D + h * HD;
    #pragma unroll
    for (int mt = 0; mt < 2; mt++) {
        #pragma unroll
        for (int rr = 0; rr < 2; rr++) {
            int r = wm * 32 + mt * 16 + g + rr * 8;
            float inv = 1.0f / rsb[r];
            #pragma unroll
            for (int nt = 0; nt < 4; nt++) {
                int c = wn * 32 + nt * 8 + q4 * 2;
                *reinterpret_cast<float2*>(Cg + (size_t)r * D + c) =
                    make_float2(acc[mt][rr * 2 + 0 >= 0 ? nt : nt][rr * 2 + 0] * inv,
                                acc[mt][nt][rr * 2 + 1] * inv);
            }
        }
    }
}

// ---------------- launch -----------------------------------------------------
extern "C" void kernel_launch(void* const* d_in, const int* in_sizes, int n_in,
                              void* d_out, int out_size) {
    const float* inputs = (const float*)d_in[0];
    const float* pos    = (const float*)d_in[1];
    const float* gamma  = (const float*)d_in[2];
    const float* beta   = (const float*)d_in[3];
    const float* wq     = (const float*)d_in[4];
    const float* bq     = (const float*)d_in[5];
    const float* wk     = (const float*)d_in[6];
    const float* bk     = (const float*)d_in[7];
    const float* wv     = (const float*)d_in[8];
    const float* bv     = (const float*)d_in[9];
    const float* wpos   = (const float*)d_in[10];
    const float* u      = (const float*)d_in[11];
    const float* vb     = (const float*)d_in[12];
    const float* wo     = (const float*)d_in[13];
    const float* bo     = (const float*)d_in[14];
    float* out = (float*)d_out;

    float *xn, *qu, *qv, *kx, *vx, *px, *ctx, *sc, *bd, *rsum;
    cudaGetSymbolAddress((void**)&xn,   g_xn);
    cudaGetSymbolAddress((void**)&qu,   g_qu);
    cudaGetSymbolAddress((void**)&qv,   g_qv);
    cudaGetSymbolAddress((void**)&kx,   g_k);
    cudaGetSymbolAddress((void**)&vx,   g_v);
    cudaGetSymbolAddress((void**)&px,   g_p);
    cudaGetSymbolAddress((void**)&ctx,  g_ctx);
    cudaGetSymbolAddress((void**)&sc,   g_expP);
    cudaGetSymbolAddress((void**)&bd,   g_bd);
    cudaGetSymbolAddress((void**)&rsum, g_rowsum);

    const int SCORE_SMEM  = 2 * 128 * 68 * 4;            // 69632 B
    const int SCORE2_SMEM = (2 * 128 * 68 + 256) * 4;    // + redS
    cudaFuncSetAttribute(score_tf32, cudaFuncAttributeMaxDynamicSharedMemorySize, SCORE_SMEM);
    cudaFuncSetAttribute(score_softmax_tf32, cudaFuncAttributeMaxDynamicSharedMemorySize, SCORE2_SMEM);

    // 1. LayerNorm
    ln_kernel<<<M, 128>>>(inputs, gamma, beta, xn);

    // 2. Projections (tf32 MMA)
    dim3 gg(4, 64);
    sgemm512_tf32<<<gg, 256>>>(xn,  wq,   bq,      u,       nullptr, qu, vb, qv);
    sgemm512_tf32<<<gg, 256>>>(xn,  wk,   bk,      nullptr, nullptr, kx, nullptr, nullptr);
    sgemm512_tf32<<<gg, 256>>>(xn,  wv,   bv,      nullptr, nullptr, vx, nullptr, nullptr);
    sgemm512_tf32<<<gg, 256>>>(pos, wpos, nullptr, nullptr, nullptr, px, nullptr, nullptr);

    // 3. BD = (Qv) @ P^T (pre-shift positional scores)
    dim3 sg(8, NB * H);
    score_tf32<<<sg, 256, SCORE_SMEM>>>(qv, px, bd);

    // 4. fused content score + shift + exp + rowsum
    score_softmax_tf32<<<sg, 256, SCORE2_SMEM>>>(qu, kx, bd, sc, rsum);

    // 5. attn @ V with normalization
    attnv_tf32<<<dim3(8, NB * H), 256>>>(sc, vx, rsum, ctx);

    // 6. output projection + bias + residual
    sgemm512_tf32<<<gg, 256>>>(ctx, wo, bo, nullptr, inputs, out, nullptr, nullptr);
}